// round 14
// baseline (speedup 1.0000x reference)
#include <cuda_runtime.h>
#include <cuda_bf16.h>
#include <cstdint>

#define NN 10000
#define NE 320000
#define INF 512
#define H1F 256
#define H2F 64
#define NT 79              // 128-row tiles covering NN (recon)
#define NPAD (NT * 128)    // 10112
#define NTRI (NT * (NT + 1) / 2)   // 3160 triangular tiles
#define TRI_OFF(b) ((b) * NT - (b) * ((b) - 1) / 2)
#define M2T 157            // 64-row tiles covering NN
#define M2PAD (M2T * 64)   // 10048

// ---------------- scratch ----------------
__device__ float g_sup1[NN * H1F];
__device__ float g_sup2[NN * H2F];
__device__ int   g_cnt[NN];
__device__ int   g_cur[NN];
__device__ int   g_off[NN + 1];
__device__ int   g_eid[NE];
__device__ __align__(16) __nv_bfloat16 g_zhi[NPAD * H2F];    // rows >= NN stay 0 forever
__device__ __align__(16) __nv_bfloat16 g_zlo[NPAD * H2F];
__device__ __align__(16) __nv_bfloat16 g_xhi[NPAD * INF];
__device__ __align__(16) __nv_bfloat16 g_xlo[NPAD * INF];
__device__ __align__(16) __nv_bfloat16 g_w1thi[H1F * INF];   // [n][k]
__device__ __align__(16) __nv_bfloat16 g_w1tlo[H1F * INF];
__device__ __align__(16) __nv_bfloat16 g_h1hi[M2PAD * H1F];  // rows >= NN stay 0 forever
__device__ __align__(16) __nv_bfloat16 g_h1lo[M2PAD * H1F];
__device__ __align__(16) __nv_bfloat16 g_w2thi[H2F * H1F];   // [n][k]
__device__ __align__(16) __nv_bfloat16 g_w2tlo[H2F * H1F];

// ---------------- mma / async helpers ----------------
__device__ __forceinline__ uint32_t smem_u32(const void* p) {
    uint32_t a;
    asm("{ .reg .u64 t; cvta.to.shared.u64 t, %1; cvt.u32.u64 %0, t; }" : "=r"(a) : "l"(p));
    return a;
}
#define LDSM4(r, addr)                                                          \
    asm volatile("ldmatrix.sync.aligned.m8n8.x4.shared.b16 {%0,%1,%2,%3}, [%4];" \
        : "=r"((r)[0]), "=r"((r)[1]), "=r"((r)[2]), "=r"((r)[3]) : "r"(addr))
#define MMA16816(c, a, b0, b1)                                                  \
    asm volatile("mma.sync.aligned.m16n8k16.row.col.f32.bf16.bf16.f32 "         \
        "{%0,%1,%2,%3},{%4,%5,%6,%7},{%8,%9},{%0,%1,%2,%3};"                    \
        : "+f"((c)[0]), "+f"((c)[1]), "+f"((c)[2]), "+f"((c)[3])                \
        : "r"((a)[0]), "r"((a)[1]), "r"((a)[2]), "r"((a)[3]), "r"(b0), "r"(b1))
#define CP_ASYNC16(saddr, gptr) \
    asm volatile("cp.async.cg.shared.global [%0], [%1], 16;" :: "r"(saddr), "l"(gptr))
#define CP_COMMIT() asm volatile("cp.async.commit_group;")
#define CP_WAIT0()  asm volatile("cp.async.wait_group 0;")
#define CP_WAIT1()  asm volatile("cp.async.wait_group 1;")

__device__ __forceinline__ float fast_sigmoid(float x) {
    float t;
    asm("tanh.approx.f32 %0, %1;" : "=f"(t) : "f"(x * 0.5f));
    return fmaf(0.5f, t, 0.5f);
}

// ================= CSR build =================
__global__ void count_deg(const int* __restrict__ dst) {
    int e = blockIdx.x * blockDim.x + threadIdx.x;
    if (e < NE) atomicAdd(&g_cnt[dst[e]], 1);
}

__global__ __launch_bounds__(1024) void scan_offsets() {
    __shared__ int wsum[32];
    __shared__ int s_carry;
    const int tid = threadIdx.x;
    const int lane = tid & 31, w = tid >> 5;
    if (tid == 0) s_carry = 0;
    __syncthreads();
    for (int base = 0; base < NN; base += 1024) {
        int i = base + tid;
        int v = (i < NN) ? g_cnt[i] : 0;
        int incl = v;
#pragma unroll
        for (int s = 1; s < 32; s <<= 1) {
            int t = __shfl_up_sync(0xFFFFFFFFu, incl, s);
            if (lane >= s) incl += t;
        }
        if (lane == 31) wsum[w] = incl;
        __syncthreads();
        if (w == 0) {
            int x = wsum[lane];
#pragma unroll
            for (int s = 1; s < 32; s <<= 1) {
                int t = __shfl_up_sync(0xFFFFFFFFu, x, s);
                if (lane >= s) x += t;
            }
            wsum[lane] = x;
        }
        __syncthreads();
        int woff = (w > 0) ? wsum[w - 1] : 0;
        int c0 = s_carry;
        int excl = c0 + woff + incl - v;
        if (i < NN) {
            g_off[i] = excl;
            g_cur[i] = excl;
        }
        __syncthreads();
        if (tid == 0) s_carry = c0 + wsum[31];
        __syncthreads();
    }
    if (tid == 0) g_off[NN] = s_carry;
}

__global__ void fill_buckets(const int* __restrict__ dst) {
    int e = blockIdx.x * blockDim.x + threadIdx.x;
    if (e < NE) {
        int p = atomicAdd(&g_cur[dst[e]], 1);
        g_eid[p] = e;
    }
}

// ================= gather aggregation (fused bias + relu + bf16 split) =================
__global__ __launch_bounds__(256) void gather_h1(
    const float4* __restrict__ sup, const int* __restrict__ esrc,
    const float* __restrict__ ew, const float* __restrict__ bias)
{
    int node = blockIdx.x * 4 + (threadIdx.x >> 6);
    int q = threadIdx.x & 63;
    int s0 = g_off[node], s1 = g_off[node + 1];
    float4 acc = make_float4(0.f, 0.f, 0.f, 0.f);
    for (int i = s0; i < s1; i++) {
        int e = g_eid[i];
        float w = ew[e];
        int s = esrc[e];
        float4 v = sup[((size_t)s << 6) + q];
        acc.x += w * v.x; acc.y += w * v.y;
        acc.z += w * v.z; acc.w += w * v.w;
    }
    float4 b = *(const float4*)&bias[q * 4];
    acc.x = fmaxf(acc.x + b.x, 0.f);
    acc.y = fmaxf(acc.y + b.y, 0.f);
    acc.z = fmaxf(acc.z + b.z, 0.f);
    acc.w = fmaxf(acc.w + b.w, 0.f);

    int idx = node * H1F + q * 4;
    float vv[4] = { acc.x, acc.y, acc.z, acc.w };
    __nv_bfloat16 hi4[4], lo4[4];
#pragma unroll
    for (int c = 0; c < 4; c++) {
        hi4[c] = __float2bfloat16(vv[c]);
        lo4[c] = __float2bfloat16(vv[c] - __bfloat162float(hi4[c]));
    }
    *(uint2*)&g_h1hi[idx] = *(const uint2*)hi4;
    *(uint2*)&g_h1lo[idx] = *(const uint2*)lo4;
}

// gather_z fused with z hi/lo split
__global__ __launch_bounds__(256) void gather_z(
    const float4* __restrict__ sup, const int* __restrict__ esrc,
    const float* __restrict__ ew, const float* __restrict__ bias,
    float4* __restrict__ outp)
{
    int node = blockIdx.x * 16 + (threadIdx.x >> 4);
    int q = threadIdx.x & 15;
    int s0 = g_off[node], s1 = g_off[node + 1];
    float4 acc = make_float4(0.f, 0.f, 0.f, 0.f);
    for (int i = s0; i < s1; i++) {
        int e = g_eid[i];
        float w = ew[e];
        int s = esrc[e];
        float4 v = sup[((size_t)s << 4) + q];
        acc.x += w * v.x; acc.y += w * v.y;
        acc.z += w * v.z; acc.w += w * v.w;
    }
    float4 b = *(const float4*)&bias[q * 4];
    acc.x = fmaxf(acc.x + b.x, 0.f);
    acc.y = fmaxf(acc.y + b.y, 0.f);
    acc.z = fmaxf(acc.z + b.z, 0.f);
    acc.w = fmaxf(acc.w + b.w, 0.f);
    outp[((size_t)node << 4) + q] = acc;

    int idx = (node << 6) + q * 4;
    float vv[4] = { acc.x, acc.y, acc.z, acc.w };
    __nv_bfloat16 hi4[4], lo4[4];
#pragma unroll
    for (int c = 0; c < 4; c++) {
        hi4[c] = __float2bfloat16(vv[c]);
        lo4[c] = __float2bfloat16(vv[c] - __bfloat162float(hi4[c]));
    }
    *(uint2*)&g_zhi[idx] = *(const uint2*)hi4;
    *(uint2*)&g_zlo[idx] = *(const uint2*)lo4;
}

// ================= split kernels (vectorized) =================
__global__ void split_x4(const float* __restrict__ x) {
    int i4 = blockIdx.x * blockDim.x + threadIdx.x;
    if (i4 >= (NPAD * INF) / 4) return;
    int idx = i4 * 4;
    float4 v;
    if (idx < NN * INF) v = *(const float4*)(x + idx);
    else                v = make_float4(0.f, 0.f, 0.f, 0.f);
    __nv_bfloat16 hi4[4], lo4[4];
    float vv[4] = { v.x, v.y, v.z, v.w };
#pragma unroll
    for (int c = 0; c < 4; c++) {
        hi4[c] = __float2bfloat16(vv[c]);
        lo4[c] = __float2bfloat16(vv[c] - __bfloat162float(hi4[c]));
    }
    *(uint2*)&g_xhi[idx] = *(const uint2*)hi4;
    *(uint2*)&g_xlo[idx] = *(const uint2*)lo4;
}

__global__ void split_w1t(const float* __restrict__ W1) {
    int i4 = blockIdx.x * blockDim.x + threadIdx.x;
    if (i4 >= (INF * H1F) / 4) return;
    int idx = i4 * 4;
    int k = idx >> 8;
    int n = idx & 255;
    float4 v = *(const float4*)(W1 + idx);
    float vv[4] = { v.x, v.y, v.z, v.w };
#pragma unroll
    for (int c = 0; c < 4; c++) {
        __nv_bfloat16 h = __float2bfloat16(vv[c]);
        g_w1thi[(n + c) * INF + k] = h;
        g_w1tlo[(n + c) * INF + k] = __float2bfloat16(vv[c] - __bfloat162float(h));
    }
}

__global__ void split_w2t(const float* __restrict__ W2) {
    int i4 = blockIdx.x * blockDim.x + threadIdx.x;
    if (i4 >= (H1F * H2F) / 4) return;
    int idx = i4 * 4;
    int k = idx >> 6;
    int n = idx & 63;
    float4 v = *(const float4*)(W2 + idx);
    float vv[4] = { v.x, v.y, v.z, v.w };
#pragma unroll
    for (int c = 0; c < 4; c++) {
        __nv_bfloat16 h = __float2bfloat16(vv[c]);
        g_w2thi[(n + c) * H1F + k] = h;
        g_w2tlo[(n + c) * H1F + k] = __float2bfloat16(vv[c] - __bfloat162float(h));
    }
}

// ================= generic GEMM: C[.,col0:col0+64] = A @ B^T (bf16-split) =================
// BM=64, BN=64, BK=32, 256 threads, 3-stage cp.async (covers L2 latency).
#define GG_P 80
#define GG_AH 0
#define GG_AL 5120
#define GG_BH 10240
#define GG_BL 15360
#define GG_STAGE 20480
#define GG_NSTAGE 3
#define GG_SMEM (GG_NSTAGE * GG_STAGE)   // 61440 -> 3 CTAs/SM

__device__ __forceinline__ void gg_load(uint32_t sbase,
    const __nv_bfloat16* __restrict__ Ahi, const __nv_bfloat16* __restrict__ Alo,
    const __nv_bfloat16* __restrict__ Bhi, const __nv_bfloat16* __restrict__ Blo,
    int row0, int col0, int K, int k0, int tid)
{
    const int lrow = tid >> 2, c4 = (tid & 3) * 16;
    const uint32_t soff = lrow * GG_P + c4;
    CP_ASYNC16(sbase + GG_AH + soff, (const char*)(Ahi + (size_t)(row0 + lrow) * K + k0) + c4);
    CP_ASYNC16(sbase + GG_AL + soff, (const char*)(Alo + (size_t)(row0 + lrow) * K + k0) + c4);
    CP_ASYNC16(sbase + GG_BH + soff, (const char*)(Bhi + (size_t)(col0 + lrow) * K + k0) + c4);
    CP_ASYNC16(sbase + GG_BL + soff, (const char*)(Blo + (size_t)(col0 + lrow) * K + k0) + c4);
}

__global__ __launch_bounds__(256) void gemm64_mma(
    const __nv_bfloat16* __restrict__ Ahi, const __nv_bfloat16* __restrict__ Alo,
    const __nv_bfloat16* __restrict__ Bhi, const __nv_bfloat16* __restrict__ Blo,
    float* __restrict__ C, int K, int ldc)
{
    extern __shared__ char smem[];
    const int tid = threadIdx.x;
    const int wid = tid >> 5;
    const int lid = tid & 31;
    const int row0 = blockIdx.y * 64;
    const int col0 = blockIdx.x * 64;

    const int m0 = (wid >> 2) * 32;
    const int n0 = (wid & 3) * 16;

    float c[2][2][4];
#pragma unroll
    for (int i = 0; i < 2; i++)
#pragma unroll
        for (int j = 0; j < 2; j++)
#pragma unroll
            for (int r = 0; r < 4; r++) c[i][j][r] = 0.f;

    const uint32_t sb = smem_u32(smem);
    const int g8 = lid >> 3;
    const int r8 = lid & 7;
    const int nit = K >> 5;   // >= 8 for all our uses

    // prologue: stages 0 and 1 in flight
    gg_load(sb, Ahi, Alo, Bhi, Blo, row0, col0, K, 0, tid);
    CP_COMMIT();
    gg_load(sb + GG_STAGE, Ahi, Alo, Bhi, Blo, row0, col0, K, 32, tid);
    CP_COMMIT();

    int stage = 0;
    for (int it = 0; it < nit; it++) {
        // stage `it` complete: allow 1 pending group while another exists, else drain
        if (it + 1 < nit) CP_WAIT1(); else CP_WAIT0();
        __syncthreads();
        if (it + 2 < nit) {
            int ns = stage + 2; if (ns >= GG_NSTAGE) ns -= GG_NSTAGE;
            gg_load(sb + ns * GG_STAGE, Ahi, Alo, Bhi, Blo,
                    row0, col0, K, (it + 2) * 32, tid);
            CP_COMMIT();
        }
        const uint32_t st = sb + stage * GG_STAGE;

#pragma unroll
        for (int ks = 0; ks < 2; ks++) {
            const int kb = ks * 16;
            uint32_t Bh[4], Bl[4];
            {
                int rown = n0 + (g8 >> 1) * 8 + r8;
                int kcol = kb + (g8 & 1) * 8;
                uint32_t a = st + rown * GG_P + kcol * 2;
                LDSM4(Bh, a + GG_BH);
                LDSM4(Bl, a + GG_BL);
            }
            uint32_t A[2][4];
#pragma unroll
            for (int i = 0; i < 2; i++) {
                int row = m0 + 16 * i + (g8 & 1) * 8 + r8;
                int kcol = kb + (g8 >> 1) * 8;
                LDSM4(A[i], st + GG_AH + row * GG_P + kcol * 2);
            }
#pragma unroll
            for (int i = 0; i < 2; i++)
#pragma unroll
                for (int j = 0; j < 2; j++) {
                    MMA16816(c[i][j], A[i], Bh[j * 2], Bh[j * 2 + 1]);
                    MMA16816(c[i][j], A[i], Bl[j * 2], Bl[j * 2 + 1]);
                }
#pragma unroll
            for (int i = 0; i < 2; i++) {
                int row = m0 + 16 * i + (g8 & 1) * 8 + r8;
                int kcol = kb + (g8 >> 1) * 8;
                LDSM4(A[i], st + GG_AL + row * GG_P + kcol * 2);
            }
#pragma unroll
            for (int i = 0; i < 2; i++)
#pragma unroll
                for (int j = 0; j < 2; j++)
                    MMA16816(c[i][j], A[i], Bh[j * 2], Bh[j * 2 + 1]);
        }
        if (++stage == GG_NSTAGE) stage = 0;
    }

    const int g = lid >> 2, t = lid & 3;
#pragma unroll
    for (int i = 0; i < 2; i++)
#pragma unroll
        for (int j = 0; j < 2; j++) {
            int r0 = row0 + m0 + 16 * i + g;
            int cc = col0 + n0 + 8 * j + 2 * t;
            if (r0 < NN)
                *(float2*)&C[(size_t)r0 * ldc + cc] = make_float2(c[i][j][0], c[i][j][1]);
            if (r0 + 8 < NN)
                *(float2*)&C[(size_t)(r0 + 8) * ldc + cc] = make_float2(c[i][j][2], c[i][j][3]);
        }
}

// ================= recon = sigmoid(z @ z^T): 512 threads, 16 warps, 32x32 warp tiles =================
#define RC_AH 0
#define RC_AL 18432
#define RC_BH 36864
#define RC_BL 55296
#define RC_SMEM 73728
#define RC_P 133   // stage pitch in floats (odd: conflict-free scalar access)
__global__ __launch_bounds__(512, 2) void recon_mma(float* __restrict__ out) {
    int t = blockIdx.x;
    int bi = (int)((2.f * NT + 1.f -
                    sqrtf((2.f * NT + 1.f) * (2.f * NT + 1.f) - 8.f * (float)t)) * 0.5f);
    if (bi < 0) bi = 0;
    while (TRI_OFF(bi + 1) <= t) bi++;
    while (TRI_OFF(bi) > t) bi--;
    int bj = bi + (t - TRI_OFF(bi));

    extern __shared__ char smem[];
    const int tid = threadIdx.x;
    const int wid = tid >> 5;
    const int lid = tid & 31;
    const uint32_t sb = smem_u32(smem);

    // ---- prologue: 4 tiles (128 rows x 128B each), 512 threads ----
    {
        const int lrow = tid >> 2;
        const int q4 = (tid & 3) * 2;
        const __nv_bfloat16* srcs[4] = {
            g_zhi + (size_t)bi * 128 * H2F, g_zlo + (size_t)bi * 128 * H2F,
            g_zhi + (size_t)bj * 128 * H2F, g_zlo + (size_t)bj * 128 * H2F };
        const int dsto[4] = { RC_AH, RC_AL, RC_BH, RC_BL };
#pragma unroll
        for (int p = 0; p < 4; p++) {
            const uint4* s = (const uint4*)(srcs[p] + (size_t)lrow * H2F) + q4;
            uint4* d = (uint4*)(smem + dsto[p] + lrow * 144 + q4 * 16);
            d[0] = s[0];
            d[1] = s[1];
        }
    }
    __syncthreads();

    // ---- MMA: 16 warps in 4x4 grid, each 32(m) x 32(n) ----
    const int m0 = (wid >> 2) * 32;
    const int n0 = (wid & 3) * 32;
    const int g8 = lid >> 3, r8 = lid & 7;

    float c[2][4][4];
#pragma unroll
    for (int i = 0; i < 2; i++)
#pragma unroll
        for (int j = 0; j < 4; j++)
#pragma unroll
            for (int r = 0; r < 4; r++) c[i][j][r] = 0.f;

#pragma unroll
    for (int ks = 0; ks < 4; ks++) {
        const int kb = ks * 16;
        uint32_t B[2][2][4];
#pragma unroll
        for (int jp = 0; jp < 2; jp++) {
            int rown = n0 + jp * 16 + (g8 >> 1) * 8 + r8;
            int kcol = kb + (g8 & 1) * 8;
            uint32_t a = sb + rown * 144 + kcol * 2;
            LDSM4(B[0][jp], a + RC_BH);
            LDSM4(B[1][jp], a + RC_BL);
        }
        uint32_t A[2][4];
#pragma unroll
        for (int i = 0; i < 2; i++) {
            int row = m0 + 16 * i + (g8 & 1) * 8 + r8;
            int kcol = kb + (g8 >> 1) * 8;
            LDSM4(A[i], sb + RC_AH + row * 144 + kcol * 2);
        }
#pragma unroll
        for (int i = 0; i < 2; i++)
#pragma unroll
            for (int j = 0; j < 4; j++) {
                MMA16816(c[i][j], A[i], B[0][j >> 1][(j & 1) * 2], B[0][j >> 1][(j & 1) * 2 + 1]);
                MMA16816(c[i][j], A[i], B[1][j >> 1][(j & 1) * 2], B[1][j >> 1][(j & 1) * 2 + 1]);
            }
#pragma unroll
        for (int i = 0; i < 2; i++) {
            int row = m0 + 16 * i + (g8 & 1) * 8 + r8;
            int kcol = kb + (g8 >> 1) * 8;
            LDSM4(A[i], sb + RC_AL + row * 144 + kcol * 2);
        }
#pragma unroll
        for (int i = 0; i < 2; i++)
#pragma unroll
            for (int j = 0; j < 4; j++)
                MMA16816(c[i][j], A[i], B[0][j >> 1][(j & 1) * 2], B[0][j >> 1][(j & 1) * 2 + 1]);
    }

    __syncthreads();   // all LDSM done before stage reuse

    // ---- phase 1: sigmoid, direct stores, transpose-stage for mirror ----
    float* stage = (float*)smem;
    const int g = lid >> 2, tq = lid & 3;
    const bool mirror = (bj > bi);
#pragma unroll
    for (int i = 0; i < 2; i++) {
        int lr0 = m0 + 16 * i + g;
        int lr1 = lr0 + 8;
        int r0 = bi * 128 + lr0;
        int r1 = r0 + 8;
#pragma unroll
        for (int j = 0; j < 4; j++) {
            int lc0 = n0 + 8 * j + 2 * tq;
            int cc = bj * 128 + lc0;
            float s0 = fast_sigmoid(c[i][j][0]);
            float s1 = fast_sigmoid(c[i][j][1]);
            float s2 = fast_sigmoid(c[i][j][2]);
            float s3 = fast_sigmoid(c[i][j][3]);
            if (cc < NN) {
                if (r0 < NN) *(float2*)&out[(size_t)r0 * NN + cc] = make_float2(s0, s1);
                if (r1 < NN) *(float2*)&out[(size_t)r1 * NN + cc] = make_float2(s2, s3);
            }
            if (mirror) {
                stage[(lc0 + 0) * RC_P + lr0] = s0;
                stage[(lc0 + 1) * RC_P + lr0] = s1;
                stage[(lc0 + 0) * RC_P + lr1] = s2;
                stage[(lc0 + 1) * RC_P + lr1] = s3;
            }
        }
    }
    __syncthreads();

    // ---- phase 2: mirror stores (scalar LDS odd pitch, STG.128) ----
    if (mirror) {
        const int mcol = tid & 127;
        const int quarter = tid >> 7;
        int gcol = bj * 128 + mcol;
        if (gcol < NN) {
            const float* src = stage + mcol * RC_P + quarter * 32;
            float* dst = out + (size_t)gcol * NN + bi * 128 + quarter * 32;
#pragma unroll
            for (int c8 = 0; c8 < 8; c8++) {
                float4 v = make_float4(src[c8 * 4 + 0], src[c8 * 4 + 1],
                                       src[c8 * 4 + 2], src[c8 * 4 + 3]);
                *(float4*)(dst + c8 * 4) = v;
            }
        }
    }
}

// ================= launch =================
extern "C" void kernel_launch(void* const* d_in, const int* in_sizes, int n_in,
                              void* d_out, int out_size)
{
    const float* x    = (const float*)d_in[0];
    const float* W1   = (const float*)d_in[1];
    const float* b1   = (const float*)d_in[2];
    const float* W2   = (const float*)d_in[3];
    const float* b2   = (const float*)d_in[4];
    const float* ew   = (const float*)d_in[5];
    const int*   esrc = (const int*)d_in[6];
    const int*   edst = (const int*)d_in[7];

    float* out   = (float*)d_out;
    float* z     = out;               // [10000, 64]
    float* recon = out + NN * H2F;    // [10000, 10000]

    float *sup1, *sup2;
    int *cnt;
    __nv_bfloat16 *xhi, *xlo, *w1thi, *w1tlo, *h1hi, *h1lo, *w2thi, *w2tlo;
    cudaGetSymbolAddress((void**)&sup1, g_sup1);
    cudaGetSymbolAddress((void**)&sup2, g_sup2);
    cudaGetSymbolAddress((void**)&cnt,  g_cnt);
    cudaGetSymbolAddress((void**)&xhi,  g_xhi);
    cudaGetSymbolAddress((void**)&xlo,  g_xlo);
    cudaGetSymbolAddress((void**)&w1thi, g_w1thi);
    cudaGetSymbolAddress((void**)&w1tlo, g_w1tlo);
    cudaGetSymbolAddress((void**)&h1hi, g_h1hi);
    cudaGetSymbolAddress((void**)&h1lo, g_h1lo);
    cudaGetSymbolAddress((void**)&w2thi, g_w2thi);
    cudaGetSymbolAddress((void**)&w2tlo, g_w2tlo);

    cudaFuncSetAttribute(gemm64_mma, cudaFuncAttributeMaxDynamicSharedMemorySize, GG_SMEM);
    cudaFuncSetAttribute(recon_mma, cudaFuncAttributeMaxDynamicSharedMemorySize, RC_SMEM);

    // independent prep first (keeps gemm1 at the ncu capture slot)
    cudaMemsetAsync(cnt, 0, NN * sizeof(int));
    split_x4<<<((NPAD * INF) / 4 + 255) / 256, 256>>>(x);
    split_w1t<<<((INF * H1F) / 4 + 255) / 256, 256>>>(W1);
    count_deg<<<NE / 256, 256>>>(edst);

    // layer 1 GEMM (profiled slot): grid 4 x 157 = 628 CTAs
    gemm64_mma<<<dim3(H1F / 64, M2T), 256, GG_SMEM>>>(xhi, xlo, w1thi, w1tlo,
                                                      sup1, INF, H1F);

    // W2 split (independent; after gemm1 to keep the capture slot stable)
    split_w2t<<<(H1F * H2F / 4) / 256, 256>>>(W2);

    // finish CSR, then aggregate (h1 emitted as bf16 hi/lo)
    scan_offsets<<<1, 1024>>>();
    fill_buckets<<<NE / 256, 256>>>(edst);
    gather_h1<<<NN / 4, 256>>>((const float4*)sup1, esrc, ew, b1);

    // layer 2 (same generic kernel): grid 1 x 157
    gemm64_mma<<<dim3(1, M2T), 256, GG_SMEM>>>(h1hi, h1lo, w2thi, w2tlo,
                                               sup2, H1F, H2F);
    gather_z<<<NN / 16, 256>>>((const float4*)sup2, esrc, ew, b2, (float4*)z);

    // decoder (triangular grid, 512 threads)
    recon_mma<<<NTRI, 512, RC_SMEM>>>(recon);
}

// round 16
// speedup vs baseline: 1.0204x; 1.0204x over previous
#include <cuda_runtime.h>
#include <cuda_bf16.h>
#include <cstdint>

#define NN 10000
#define NE 320000
#define INF 512
#define H1F 256
#define H2F 64
#define NT 79              // 128-row tiles covering NN (recon)
#define NPAD (NT * 128)    // 10112
#define NTRI (NT * (NT + 1) / 2)   // 3160 triangular tiles
#define TRI_OFF(b) ((b) * NT - (b) * ((b) - 1) / 2)
#define M2T 157            // 64-row tiles covering NN
#define M2PAD (M2T * 64)   // 10048

// ---------------- scratch ----------------
__device__ float g_sup1[NN * H1F];
__device__ float g_sup2[NN * H2F];
__device__ int   g_cnt[NN];
__device__ int   g_cur[NN];
__device__ int   g_off[NN + 1];
__device__ int2  g_edge[NE];          // packed (src, weight-bits) bucketed by dst
__device__ __align__(16) __nv_bfloat16 g_zhi[NPAD * H2F];    // rows >= NN stay 0 forever
__device__ __align__(16) __nv_bfloat16 g_zlo[NPAD * H2F];
__device__ __align__(16) __nv_bfloat16 g_xhi[NPAD * INF];
__device__ __align__(16) __nv_bfloat16 g_xlo[NPAD * INF];
__device__ __align__(16) __nv_bfloat16 g_w1thi[H1F * INF];   // [n][k]
__device__ __align__(16) __nv_bfloat16 g_w1tlo[H1F * INF];
__device__ __align__(16) __nv_bfloat16 g_h1hi[M2PAD * H1F];  // rows >= NN stay 0 forever
__device__ __align__(16) __nv_bfloat16 g_h1lo[M2PAD * H1F];
__device__ __align__(16) __nv_bfloat16 g_w2thi[H2F * H1F];   // [n][k]
__device__ __align__(16) __nv_bfloat16 g_w2tlo[H2F * H1F];

// ---------------- mma / async helpers ----------------
__device__ __forceinline__ uint32_t smem_u32(const void* p) {
    uint32_t a;
    asm("{ .reg .u64 t; cvta.to.shared.u64 t, %1; cvt.u32.u64 %0, t; }" : "=r"(a) : "l"(p));
    return a;
}
#define LDSM4(r, addr)                                                          \
    asm volatile("ldmatrix.sync.aligned.m8n8.x4.shared.b16 {%0,%1,%2,%3}, [%4];" \
        : "=r"((r)[0]), "=r"((r)[1]), "=r"((r)[2]), "=r"((r)[3]) : "r"(addr))
#define MMA16816(c, a, b0, b1)                                                  \
    asm volatile("mma.sync.aligned.m16n8k16.row.col.f32.bf16.bf16.f32 "         \
        "{%0,%1,%2,%3},{%4,%5,%6,%7},{%8,%9},{%0,%1,%2,%3};"                    \
        : "+f"((c)[0]), "+f"((c)[1]), "+f"((c)[2]), "+f"((c)[3])                \
        : "r"((a)[0]), "r"((a)[1]), "r"((a)[2]), "r"((a)[3]), "r"(b0), "r"(b1))
#define CP_ASYNC16(saddr, gptr) \
    asm volatile("cp.async.cg.shared.global [%0], [%1], 16;" :: "r"(saddr), "l"(gptr))
#define CP_COMMIT() asm volatile("cp.async.commit_group;")
#define CP_WAIT0()  asm volatile("cp.async.wait_group 0;")

__device__ __forceinline__ float fast_sigmoid(float x) {
    float t;
    asm("tanh.approx.f32 %0, %1;" : "=f"(t) : "f"(x * 0.5f));
    return fmaf(0.5f, t, 0.5f);
}

// ================= CSR build =================
__global__ void count_deg(const int* __restrict__ dst) {
    int e = blockIdx.x * blockDim.x + threadIdx.x;
    if (e < NE) atomicAdd(&g_cnt[dst[e]], 1);
}

// single-pass scan: each thread owns 10 counts, one block scan total
__global__ __launch_bounds__(1024) void scan_offsets() {
    __shared__ int wsum[32];
    const int tid = threadIdx.x;
    const int lane = tid & 31, w = tid >> 5;
    const int base = tid * 10;

    int local[10];
    int tsum = 0;
#pragma unroll
    for (int j = 0; j < 10; j++) {
        int i = base + j;
        int v = (i < NN) ? g_cnt[i] : 0;
        local[j] = tsum;      // exclusive prefix within thread
        tsum += v;
    }

    // block exclusive scan of tsum
    int incl = tsum;
#pragma unroll
    for (int s = 1; s < 32; s <<= 1) {
        int t = __shfl_up_sync(0xFFFFFFFFu, incl, s);
        if (lane >= s) incl += t;
    }
    if (lane == 31) wsum[w] = incl;
    __syncthreads();
    if (w == 0) {
        int x = (lane < 32) ? wsum[lane] : 0;
#pragma unroll
        for (int s = 1; s < 32; s <<= 1) {
            int t = __shfl_up_sync(0xFFFFFFFFu, x, s);
            if (lane >= s) x += t;
        }
        wsum[lane] = x;
    }
    __syncthreads();
    int toff = ((w > 0) ? wsum[w - 1] : 0) + incl - tsum;   // exclusive offset for thread

#pragma unroll
    for (int j = 0; j < 10; j++) {
        int i = base + j;
        if (i < NN) {
            int o = toff + local[j];
            g_off[i] = o;
            g_cur[i] = o;
        }
    }
    if (tid == 1023) g_off[NN] = wsum[31];
}

__global__ void fill_buckets(const int* __restrict__ src, const int* __restrict__ dst,
                             const float* __restrict__ ew) {
    int e = blockIdx.x * blockDim.x + threadIdx.x;
    if (e < NE) {
        int p = atomicAdd(&g_cur[dst[e]], 1);
        g_edge[p] = make_int2(src[e], __float_as_int(ew[e]));
    }
}

// ================= gather aggregation (fused bias + relu + bf16 split) =================
__global__ __launch_bounds__(256) void gather_h1(
    const float4* __restrict__ sup, const float* __restrict__ bias)
{
    int node = blockIdx.x * 4 + (threadIdx.x >> 6);
    int q = threadIdx.x & 63;
    int s0 = g_off[node], s1 = g_off[node + 1];
    float4 acc = make_float4(0.f, 0.f, 0.f, 0.f);
    for (int i = s0; i < s1; i++) {
        int2 ed = g_edge[i];
        float w = __int_as_float(ed.y);
        float4 v = sup[((size_t)ed.x << 6) + q];
        acc.x += w * v.x; acc.y += w * v.y;
        acc.z += w * v.z; acc.w += w * v.w;
    }
    float4 b = *(const float4*)&bias[q * 4];
    acc.x = fmaxf(acc.x + b.x, 0.f);
    acc.y = fmaxf(acc.y + b.y, 0.f);
    acc.z = fmaxf(acc.z + b.z, 0.f);
    acc.w = fmaxf(acc.w + b.w, 0.f);

    int idx = node * H1F + q * 4;
    float vv[4] = { acc.x, acc.y, acc.z, acc.w };
    __nv_bfloat16 hi4[4], lo4[4];
#pragma unroll
    for (int c = 0; c < 4; c++) {
        hi4[c] = __float2bfloat16(vv[c]);
        lo4[c] = __float2bfloat16(vv[c] - __bfloat162float(hi4[c]));
    }
    *(uint2*)&g_h1hi[idx] = *(const uint2*)hi4;
    *(uint2*)&g_h1lo[idx] = *(const uint2*)lo4;
}

// gather_z fused with z hi/lo split
__global__ __launch_bounds__(256) void gather_z(
    const float4* __restrict__ sup, const float* __restrict__ bias,
    float4* __restrict__ outp)
{
    int node = blockIdx.x * 16 + (threadIdx.x >> 4);
    int q = threadIdx.x & 15;
    int s0 = g_off[node], s1 = g_off[node + 1];
    float4 acc = make_float4(0.f, 0.f, 0.f, 0.f);
    for (int i = s0; i < s1; i++) {
        int2 ed = g_edge[i];
        float w = __int_as_float(ed.y);
        float4 v = sup[((size_t)ed.x << 4) + q];
        acc.x += w * v.x; acc.y += w * v.y;
        acc.z += w * v.z; acc.w += w * v.w;
    }
    float4 b = *(const float4*)&bias[q * 4];
    acc.x = fmaxf(acc.x + b.x, 0.f);
    acc.y = fmaxf(acc.y + b.y, 0.f);
    acc.z = fmaxf(acc.z + b.z, 0.f);
    acc.w = fmaxf(acc.w + b.w, 0.f);
    outp[((size_t)node << 4) + q] = acc;

    int idx = (node << 6) + q * 4;
    float vv[4] = { acc.x, acc.y, acc.z, acc.w };
    __nv_bfloat16 hi4[4], lo4[4];
#pragma unroll
    for (int c = 0; c < 4; c++) {
        hi4[c] = __float2bfloat16(vv[c]);
        lo4[c] = __float2bfloat16(vv[c] - __bfloat162float(hi4[c]));
    }
    *(uint2*)&g_zhi[idx] = *(const uint2*)hi4;
    *(uint2*)&g_zlo[idx] = *(const uint2*)lo4;
}

// ================= split kernels (vectorized) =================
__global__ void split_x4(const float* __restrict__ x) {
    int i4 = blockIdx.x * blockDim.x + threadIdx.x;
    if (i4 >= (NPAD * INF) / 4) return;
    int idx = i4 * 4;
    float4 v;
    if (idx < NN * INF) v = *(const float4*)(x + idx);
    else                v = make_float4(0.f, 0.f, 0.f, 0.f);
    __nv_bfloat16 hi4[4], lo4[4];
    float vv[4] = { v.x, v.y, v.z, v.w };
#pragma unroll
    for (int c = 0; c < 4; c++) {
        hi4[c] = __float2bfloat16(vv[c]);
        lo4[c] = __float2bfloat16(vv[c] - __bfloat162float(hi4[c]));
    }
    *(uint2*)&g_xhi[idx] = *(const uint2*)hi4;
    *(uint2*)&g_xlo[idx] = *(const uint2*)lo4;
}

__global__ void split_w1t(const float* __restrict__ W1) {
    int i4 = blockIdx.x * blockDim.x + threadIdx.x;
    if (i4 >= (INF * H1F) / 4) return;
    int idx = i4 * 4;
    int k = idx >> 8;
    int n = idx & 255;
    float4 v = *(const float4*)(W1 + idx);
    float vv[4] = { v.x, v.y, v.z, v.w };
#pragma unroll
    for (int c = 0; c < 4; c++) {
        __nv_bfloat16 h = __float2bfloat16(vv[c]);
        g_w1thi[(n + c) * INF + k] = h;
        g_w1tlo[(n + c) * INF + k] = __float2bfloat16(vv[c] - __bfloat162float(h));
    }
}

__global__ void split_w2t(const float* __restrict__ W2) {
    int i4 = blockIdx.x * blockDim.x + threadIdx.x;
    if (i4 >= (H1F * H2F) / 4) return;
    int idx = i4 * 4;
    int k = idx >> 6;
    int n = idx & 63;
    float4 v = *(const float4*)(W2 + idx);
    float vv[4] = { v.x, v.y, v.z, v.w };
#pragma unroll
    for (int c = 0; c < 4; c++) {
        __nv_bfloat16 h = __float2bfloat16(vv[c]);
        g_w2thi[(n + c) * H1F + k] = h;
        g_w2tlo[(n + c) * H1F + k] = __float2bfloat16(vv[c] - __bfloat162float(h));
    }
}

// ================= generic GEMM: C[.,col0:col0+64] = A @ B^T (bf16-split) =================
// BM=64, BN=64, BK=32, 256 threads, 2-stage cp.async. pitch 80B conflict-free.
#define GG_P 80
#define GG_AH 0
#define GG_AL 5120
#define GG_BH 10240
#define GG_BL 15360
#define GG_STAGE 20480
#define GG_SMEM (2 * GG_STAGE)

__device__ __forceinline__ void gg_load(uint32_t sbase,
    const __nv_bfloat16* __restrict__ Ahi, const __nv_bfloat16* __restrict__ Alo,
    const __nv_bfloat16* __restrict__ Bhi, const __nv_bfloat16* __restrict__ Blo,
    int row0, int col0, int K, int k0, int tid)
{
    const int lrow = tid >> 2, c4 = (tid & 3) * 16;
    const uint32_t soff = lrow * GG_P + c4;
    CP_ASYNC16(sbase + GG_AH + soff, (const char*)(Ahi + (size_t)(row0 + lrow) * K + k0) + c4);
    CP_ASYNC16(sbase + GG_AL + soff, (const char*)(Alo + (size_t)(row0 + lrow) * K + k0) + c4);
    CP_ASYNC16(sbase + GG_BH + soff, (const char*)(Bhi + (size_t)(col0 + lrow) * K + k0) + c4);
    CP_ASYNC16(sbase + GG_BL + soff, (const char*)(Blo + (size_t)(col0 + lrow) * K + k0) + c4);
}

__global__ __launch_bounds__(256) void gemm64_mma(
    const __nv_bfloat16* __restrict__ Ahi, const __nv_bfloat16* __restrict__ Alo,
    const __nv_bfloat16* __restrict__ Bhi, const __nv_bfloat16* __restrict__ Blo,
    float* __restrict__ C, int K, int ldc)
{
    extern __shared__ char smem[];
    const int tid = threadIdx.x;
    const int wid = tid >> 5;
    const int lid = tid & 31;
    const int row0 = blockIdx.y * 64;
    const int col0 = blockIdx.x * 64;

    const int m0 = (wid >> 2) * 32;
    const int n0 = (wid & 3) * 16;

    float c[2][2][4];
#pragma unroll
    for (int i = 0; i < 2; i++)
#pragma unroll
        for (int j = 0; j < 2; j++)
#pragma unroll
            for (int r = 0; r < 4; r++) c[i][j][r] = 0.f;

    const uint32_t sb = smem_u32(smem);
    const int g8 = lid >> 3;
    const int r8 = lid & 7;
    const int nit = K >> 5;

    gg_load(sb, Ahi, Alo, Bhi, Blo, row0, col0, K, 0, tid);
    CP_COMMIT();

    for (int it = 0; it < nit; it++) {
        CP_WAIT0();
        __syncthreads();
        if (it + 1 < nit) {
            gg_load(sb + ((it + 1) & 1) * GG_STAGE, Ahi, Alo, Bhi, Blo,
                    row0, col0, K, (it + 1) * 32, tid);
            CP_COMMIT();
        }
        const uint32_t st = sb + (it & 1) * GG_STAGE;

#pragma unroll
        for (int ks = 0; ks < 2; ks++) {
            const int kb = ks * 16;
            uint32_t Bh[4], Bl[4];
            {
                int rown = n0 + (g8 >> 1) * 8 + r8;
                int kcol = kb + (g8 & 1) * 8;
                uint32_t a = st + rown * GG_P + kcol * 2;
                LDSM4(Bh, a + GG_BH);
                LDSM4(Bl, a + GG_BL);
            }
            uint32_t A[2][4];
#pragma unroll
            for (int i = 0; i < 2; i++) {
                int row = m0 + 16 * i + (g8 & 1) * 8 + r8;
                int kcol = kb + (g8 >> 1) * 8;
                LDSM4(A[i], st + GG_AH + row * GG_P + kcol * 2);
            }
#pragma unroll
            for (int i = 0; i < 2; i++)
#pragma unroll
                for (int j = 0; j < 2; j++) {
                    MMA16816(c[i][j], A[i], Bh[j * 2], Bh[j * 2 + 1]);
                    MMA16816(c[i][j], A[i], Bl[j * 2], Bl[j * 2 + 1]);
                }
#pragma unroll
            for (int i = 0; i < 2; i++) {
                int row = m0 + 16 * i + (g8 & 1) * 8 + r8;
                int kcol = kb + (g8 >> 1) * 8;
                LDSM4(A[i], st + GG_AL + row * GG_P + kcol * 2);
            }
#pragma unroll
            for (int i = 0; i < 2; i++)
#pragma unroll
                for (int j = 0; j < 2; j++)
                    MMA16816(c[i][j], A[i], Bh[j * 2], Bh[j * 2 + 1]);
        }
    }

    const int g = lid >> 2, t = lid & 3;
#pragma unroll
    for (int i = 0; i < 2; i++)
#pragma unroll
        for (int j = 0; j < 2; j++) {
            int r0 = row0 + m0 + 16 * i + g;
            int cc = col0 + n0 + 8 * j + 2 * t;
            if (r0 < NN)
                *(float2*)&C[(size_t)r0 * ldc + cc] = make_float2(c[i][j][0], c[i][j][1]);
            if (r0 + 8 < NN)
                *(float2*)&C[(size_t)(r0 + 8) * ldc + cc] = make_float2(c[i][j][2], c[i][j][3]);
        }
}

// ================= recon = sigmoid(z @ z^T): 512 threads, 16 warps, 32x32 warp tiles =================
#define RC_AH 0
#define RC_AL 18432
#define RC_BH 36864
#define RC_BL 55296
#define RC_SMEM 73728
#define RC_P 133   // stage pitch in floats (odd: conflict-free scalar access)
__global__ __launch_bounds__(512, 2) void recon_mma(float* __restrict__ out) {
    int t = blockIdx.x;
    int bi = (int)((2.f * NT + 1.f -
                    sqrtf((2.f * NT + 1.f) * (2.f * NT + 1.f) - 8.f * (float)t)) * 0.5f);
    if (bi < 0) bi = 0;
    while (TRI_OFF(bi + 1) <= t) bi++;
    while (TRI_OFF(bi) > t) bi--;
    int bj = bi + (t - TRI_OFF(bi));

    extern __shared__ char smem[];
    const int tid = threadIdx.x;
    const int wid = tid >> 5;
    const int lid = tid & 31;
    const uint32_t sb = smem_u32(smem);

    {
        const int lrow = tid >> 2;
        const int q4 = (tid & 3) * 2;
        const __nv_bfloat16* srcs[4] = {
            g_zhi + (size_t)bi * 128 * H2F, g_zlo + (size_t)bi * 128 * H2F,
            g_zhi + (size_t)bj * 128 * H2F, g_zlo + (size_t)bj * 128 * H2F };
        const int dsto[4] = { RC_AH, RC_AL, RC_BH, RC_BL };
#pragma unroll
        for (int p = 0; p < 4; p++) {
            const uint4* s = (const uint4*)(srcs[p] + (size_t)lrow * H2F) + q4;
            uint4* d = (uint4*)(smem + dsto[p] + lrow * 144 + q4 * 16);
            d[0] = s[0];
            d[1] = s[1];
        }
    }
    __syncthreads();

    const int m0 = (wid >> 2) * 32;
    const int n0 = (wid & 3) * 32;
    const int g8 = lid >> 3, r8 = lid & 7;

    float c[2][4][4];
#pragma unroll
    for (int i = 0; i < 2; i++)
#pragma unroll
        for (int j = 0; j < 4; j++)
#pragma unroll
            for (int r = 0; r < 4; r++) c[i][j][r] = 0.f;

#pragma unroll
    for (int ks = 0; ks < 4; ks++) {
        const int kb = ks * 16;
        uint32_t B[2][2][4];
#pragma unroll
        for (int jp = 0; jp < 2; jp++) {
            int rown = n0 + jp * 16 + (g8 >> 1) * 8 + r8;
            int kcol = kb + (g8 & 1) * 8;
            uint32_t a = sb + rown * 144 + kcol * 2;
            LDSM4(B[0][jp], a + RC_BH);
            LDSM4(B[1][jp], a + RC_BL);
        }
        uint32_t A[2][4];
#pragma unroll
        for (int i = 0; i < 2; i++) {
            int row = m0 + 16 * i + (g8 & 1) * 8 + r8;
            int kcol = kb + (g8 >> 1) * 8;
            LDSM4(A[i], sb + RC_AH + row * 144 + kcol * 2);
        }
#pragma unroll
        for (int i = 0; i < 2; i++)
#pragma unroll
            for (int j = 0; j < 4; j++) {
                MMA16816(c[i][j], A[i], B[0][j >> 1][(j & 1) * 2], B[0][j >> 1][(j & 1) * 2 + 1]);
                MMA16816(c[i][j], A[i], B[1][j >> 1][(j & 1) * 2], B[1][j >> 1][(j & 1) * 2 + 1]);
            }
#pragma unroll
        for (int i = 0; i < 2; i++) {
            int row = m0 + 16 * i + (g8 & 1) * 8 + r8;
            int kcol = kb + (g8 >> 1) * 8;
            LDSM4(A[i], sb + RC_AL + row * 144 + kcol * 2);
        }
#pragma unroll
        for (int i = 0; i < 2; i++)
#pragma unroll
            for (int j = 0; j < 4; j++)
                MMA16816(c[i][j], A[i], B[0][j >> 1][(j & 1) * 2], B[0][j >> 1][(j & 1) * 2 + 1]);
    }

    __syncthreads();

    float* stage = (float*)smem;
    const int g = lid >> 2, tq = lid & 3;
    const bool mirror = (bj > bi);
#pragma unroll
    for (int i = 0; i < 2; i++) {
        int lr0 = m0 + 16 * i + g;
        int lr1 = lr0 + 8;
        int r0 = bi * 128 + lr0;
        int r1 = r0 + 8;
#pragma unroll
        for (int j = 0; j < 4; j++) {
            int lc0 = n0 + 8 * j + 2 * tq;
            int cc = bj * 128 + lc0;
            float s0 = fast_sigmoid(c[i][j][0]);
            float s1 = fast_sigmoid(c[i][j][1]);
            float s2 = fast_sigmoid(c[i][j][2]);
            float s3 = fast_sigmoid(c[i][j][3]);
            if (cc < NN) {
                if (r0 < NN) *(float2*)&out[(size_t)r0 * NN + cc] = make_float2(s0, s1);
                if (r1 < NN) *(float2*)&out[(size_t)r1 * NN + cc] = make_float2(s2, s3);
            }
            if (mirror) {
                stage[(lc0 + 0) * RC_P + lr0] = s0;
                stage[(lc0 + 1) * RC_P + lr0] = s1;
                stage[(lc0 + 0) * RC_P + lr1] = s2;
                stage[(lc0 + 1) * RC_P + lr1] = s3;
            }
        }
    }
    __syncthreads();

    if (mirror) {
        const int mcol = tid & 127;
        const int quarter = tid >> 7;
        int gcol = bj * 128 + mcol;
        if (gcol < NN) {
            const float* src = stage + mcol * RC_P + quarter * 32;
            float* dst = out + (size_t)gcol * NN + bi * 128 + quarter * 32;
#pragma unroll
            for (int c8 = 0; c8 < 8; c8++) {
                float4 v = make_float4(src[c8 * 4 + 0], src[c8 * 4 + 1],
                                       src[c8 * 4 + 2], src[c8 * 4 + 3]);
                *(float4*)(dst + c8 * 4) = v;
            }
        }
    }
}

// ================= launch =================
extern "C" void kernel_launch(void* const* d_in, const int* in_sizes, int n_in,
                              void* d_out, int out_size)
{
    const float* x    = (const float*)d_in[0];
    const float* W1   = (const float*)d_in[1];
    const float* b1   = (const float*)d_in[2];
    const float* W2   = (const float*)d_in[3];
    const float* b2   = (const float*)d_in[4];
    const float* ew   = (const float*)d_in[5];
    const int*   esrc = (const int*)d_in[6];
    const int*   edst = (const int*)d_in[7];

    float* out   = (float*)d_out;
    float* z     = out;               // [10000, 64]
    float* recon = out + NN * H2F;    // [10000, 10000]

    float *sup1, *sup2;
    int *cnt;
    __nv_bfloat16 *xhi, *xlo, *w1thi, *w1tlo, *h1hi, *h1lo, *w2thi, *w2tlo;
    cudaGetSymbolAddress((void**)&sup1, g_sup1);
    cudaGetSymbolAddress((void**)&sup2, g_sup2);
    cudaGetSymbolAddress((void**)&cnt,  g_cnt);
    cudaGetSymbolAddress((void**)&xhi,  g_xhi);
    cudaGetSymbolAddress((void**)&xlo,  g_xlo);
    cudaGetSymbolAddress((void**)&w1thi, g_w1thi);
    cudaGetSymbolAddress((void**)&w1tlo, g_w1tlo);
    cudaGetSymbolAddress((void**)&h1hi, g_h1hi);
    cudaGetSymbolAddress((void**)&h1lo, g_h1lo);
    cudaGetSymbolAddress((void**)&w2thi, g_w2thi);
    cudaGetSymbolAddress((void**)&w2tlo, g_w2tlo);

    cudaFuncSetAttribute(gemm64_mma, cudaFuncAttributeMaxDynamicSharedMemorySize, GG_SMEM);
    cudaFuncSetAttribute(recon_mma, cudaFuncAttributeMaxDynamicSharedMemorySize, RC_SMEM);

    // independent prep first (keeps gemm1 at the ncu capture slot)
    cudaMemsetAsync(cnt, 0, NN * sizeof(int));
    split_x4<<<((NPAD * INF) / 4 + 255) / 256, 256>>>(x);
    split_w1t<<<((INF * H1F) / 4 + 255) / 256, 256>>>(W1);
    count_deg<<<NE / 256, 256>>>(edst);

    // layer 1 GEMM (profiled slot): grid 4 x 157 = 628 CTAs
    gemm64_mma<<<dim3(H1F / 64, M2T), 256, GG_SMEM>>>(xhi, xlo, w1thi, w1tlo,
                                                      sup1, INF, H1F);

    // W2 split (independent; after gemm1 to keep the capture slot stable)
    split_w2t<<<(H1F * H2F / 4) / 256, 256>>>(W2);

    // finish CSR (packed edges), then aggregate (h1 emitted as bf16 hi/lo)
    scan_offsets<<<1, 1024>>>();
    fill_buckets<<<NE / 256, 256>>>(esrc, edst, ew);
    gather_h1<<<NN / 4, 256>>>((const float4*)sup1, b1);

    // layer 2 (same generic kernel): grid 1 x 157
    gemm64_mma<<<dim3(1, M2T), 256, GG_SMEM>>>(h1hi, h1lo, w2thi, w2tlo,
                                               sup2, H1F, H2F);
    gather_z<<<NN / 16, 256>>>((const float4*)sup2, b2, (float4*)z);

    // decoder (triangular grid, 512 threads)
    recon_mma<<<NTRI, 512, RC_SMEM>>>(recon);
}